// round 3
// baseline (speedup 1.0000x reference)
#include <cuda_runtime.h>
#include <math.h>

#define NN 1024
#define FD 32
#define ED 20
#define JT 64   // j-tile per iteration

// Scratch for precomputed msg_left output: left[j, 96]
__device__ float g_left[NN * 96];

// ---------------------------------------------------------------------------
// Kernel 1: left[j,:] = silu(scalar[j] @ mL_w1 + b1) @ mL_w2 + b2   (per node)
// grid = NN, block = 96
// ---------------------------------------------------------------------------
__global__ void left_kernel(const float* __restrict__ scalar,
                            const float* __restrict__ w1, const float* __restrict__ b1,
                            const float* __restrict__ w2, const float* __restrict__ b2) {
    int j = blockIdx.x;
    int t = threadIdx.x;
    __shared__ float ss[FD];
    __shared__ float sh[FD];
    if (t < FD) ss[t] = scalar[j * FD + t];
    __syncthreads();
    if (t < FD) {
        float acc = b1[t];
#pragma unroll
        for (int k = 0; k < FD; k++) acc += ss[k] * w1[k * FD + t];
        sh[t] = acc / (1.0f + expf(-acc));   // silu
    }
    __syncthreads();
    float acc = b2[t];
#pragma unroll
    for (int k = 0; k < FD; k++) acc += sh[k] * w2[k * 96 + t];
    g_left[j * 96 + t] = acc;
}

// ---------------------------------------------------------------------------
// Kernel 2: fused message-reduction + update, one CTA per node i.
// block = 256 (8 warps). Each warp handles 8 j's per 64-j tile; lane = feature.
// ---------------------------------------------------------------------------
__global__ void __launch_bounds__(256)
main_kernel(const float* __restrict__ scalar, const float* __restrict__ vector,
            const float* __restrict__ expansion, const float* __restrict__ direction,
            const float* __restrict__ mask,
            const float* __restrict__ mRw, const float* __restrict__ mRb,
            const float* __restrict__ uRw1, const float* __restrict__ uRb1,
            const float* __restrict__ uRw2, const float* __restrict__ uRb2,
            const float* __restrict__ Uw, const float* __restrict__ Vw,
            float* __restrict__ out) {
    int i = blockIdx.x;
    int tid = threadIdx.x;
    int warp = tid >> 5, lane = tid & 31;

    __shared__ float sX[JT * ED];      // expansion tile
    __shared__ float sMask[JT];
    __shared__ float sDir[JT * 3];
    __shared__ float red[8][4][32];    // per-warp partial accumulators
    __shared__ float ds[32], dv[96];
    __shared__ float s_new[32], v_new[96], lu[96], ru[96], feats[64], hbuf[32], og[96];

    // mR_w columns owned by this lane, in registers (60 regs).
    float wa[ED], wb[ED], wc[ED];
#pragma unroll
    for (int e = 0; e < ED; e++) {
        wa[e] = mRw[e * 96 + lane];
        wb[e] = mRw[e * 96 + 32 + lane];
        wc[e] = mRw[e * 96 + 64 + lane];
    }
    const float rba = mRb[lane], rbb = mRb[32 + lane], rbc = mRb[64 + lane];

    float acc_s = 0.f, acc_v0 = 0.f, acc_v1 = 0.f, acc_v2 = 0.f;

    const float* Xrow = expansion + (size_t)i * NN * ED;
    const float* Mrow = mask + (size_t)i * NN;
    const float* Drow = direction + (size_t)i * NN * 3;

    for (int j0 = 0; j0 < NN; j0 += JT) {
        __syncthreads();   // previous tile fully consumed
        // cooperative tile loads (all contiguous, float4)
        {
            const float4* src = (const float4*)(Xrow + j0 * ED);
            float4* dst = (float4*)sX;
#pragma unroll
            for (int k = tid; k < JT * ED / 4; k += 256) dst[k] = src[k];
            if (tid < JT) sMask[tid] = Mrow[j0 + tid];
            if (tid < JT * 3 / 4) ((float4*)sDir)[tid] = ((const float4*)(Drow + j0 * 3))[tid];
        }
        __syncthreads();

#pragma unroll 4
        for (int t = 0; t < 8; t++) {
            int jj = warp * 8 + t;
            int j = j0 + jj;
            // 20->96 matvec for this (i,j): lane owns (f, 32+f, 64+f)
            float ra = rba, rb = rbb, rc = rbc;
#pragma unroll
            for (int e = 0; e < ED; e++) {
                float x = sX[jj * ED + e];     // broadcast LDS
                ra += x * wa[e];
                rb += x * wb[e];
                rc += x * wc[e];
            }
            const float* L = g_left + j * 96;
            float pa = L[lane] * ra;
            float pb = L[32 + lane] * rb;
            float pc = L[64 + lane] * rc;
            float m = sMask[jj];
            acc_s += m * pb;
            float mpa = m * pa, mpc = m * pc;
            const float* V = vector + j * 96;
            acc_v0 += V[lane]      * mpa + sDir[jj * 3 + 0] * mpc;
            acc_v1 += V[32 + lane] * mpa + sDir[jj * 3 + 1] * mpc;
            acc_v2 += V[64 + lane] * mpa + sDir[jj * 3 + 2] * mpc;
        }
    }

    // cross-warp reduction
    red[warp][0][lane] = acc_s;
    red[warp][1][lane] = acc_v0;
    red[warp][2][lane] = acc_v1;
    red[warp][3][lane] = acc_v2;
    __syncthreads();
    if (tid < 128) {
        int a = tid >> 5, f = tid & 31;
        float s = 0.f;
#pragma unroll
        for (int w = 0; w < 8; w++) s += red[w][a][f];
        if (a == 0) ds[f] = s; else dv[(a - 1) * 32 + f] = s;
    }
    __syncthreads();

    // ---- update phase (per-node, tiny) ----
    if (tid < 32) s_new[tid] = scalar[i * 32 + tid] + ds[tid];
    if (tid < 96) v_new[tid] = vector[i * 96 + tid] + dv[tid];
    __syncthreads();

    if (tid < 96) {  // left = v_new @ U_w, right = v_new @ V_w
        int d = tid >> 5, f = tid & 31;
        float a1 = 0.f, a2 = 0.f;
#pragma unroll
        for (int k = 0; k < 32; k++) {
            float v = v_new[d * 32 + k];
            a1 += v * Uw[k * 32 + f];
            a2 += v * Vw[k * 32 + f];
        }
        lu[tid] = a1;
        ru[tid] = a2;
    }
    __syncthreads();
    if (tid < 32) {
        float r0 = ru[tid], r1 = ru[32 + tid], r2 = ru[64 + tid];
        feats[tid] = s_new[tid];
        feats[32 + tid] = sqrtf(r0 * r0 + r1 * r1 + r2 * r2);
    }
    __syncthreads();
    if (tid < 32) {
        float acc = uRb1[tid];
#pragma unroll
        for (int k = 0; k < 64; k++) acc += feats[k] * uRw1[k * 32 + tid];
        hbuf[tid] = acc / (1.0f + expf(-acc));   // silu
    }
    __syncthreads();
    if (tid < 96) {
        float acc = uRb2[tid];
#pragma unroll
        for (int k = 0; k < 32; k++) acc += hbuf[k] * uRw2[k * 96 + tid];
        og[tid] = acc;
    }
    __syncthreads();
    if (tid < 32) {  // scalar out: s_new + inner*b + c
        float inner = lu[tid] * ru[tid] + lu[32 + tid] * ru[32 + tid] + lu[64 + tid] * ru[64 + tid];
        out[i * 32 + tid] = s_new[tid] + inner * og[32 + tid] + og[64 + tid];
    }
    if (tid < 96) {  // vector out: v_new + a*left
        out[NN * 32 + i * 96 + tid] = v_new[tid] + og[tid & 31] * lu[tid];
    }
}

// ---------------------------------------------------------------------------
// launch
// inputs (metadata order): 0 scalar, 1 vector, 2 expansion, 3 direction, 4 mask,
// 5 mL_w1, 6 mL_b1, 7 mL_w2, 8 mL_b2, 9 mR_w, 10 mR_b,
// 11 uR_w1, 12 uR_b1, 13 uR_w2, 14 uR_b2, 15 U_w, 16 V_w
// output: [scalar_out (1024*32) | vector_out (1024*96)] fp32
// ---------------------------------------------------------------------------
extern "C" void kernel_launch(void* const* d_in, const int* in_sizes, int n_in,
                              void* d_out, int out_size) {
    const float* scalar    = (const float*)d_in[0];
    const float* vector    = (const float*)d_in[1];
    const float* expansion = (const float*)d_in[2];
    const float* direction = (const float*)d_in[3];
    const float* mask      = (const float*)d_in[4];
    const float* mL_w1 = (const float*)d_in[5];
    const float* mL_b1 = (const float*)d_in[6];
    const float* mL_w2 = (const float*)d_in[7];
    const float* mL_b2 = (const float*)d_in[8];
    const float* mR_w  = (const float*)d_in[9];
    const float* mR_b  = (const float*)d_in[10];
    const float* uR_w1 = (const float*)d_in[11];
    const float* uR_b1 = (const float*)d_in[12];
    const float* uR_w2 = (const float*)d_in[13];
    const float* uR_b2 = (const float*)d_in[14];
    const float* U_w   = (const float*)d_in[15];
    const float* V_w   = (const float*)d_in[16];
    float* out = (float*)d_out;

    left_kernel<<<NN, 96>>>(scalar, mL_w1, mL_b1, mL_w2, mL_b2);
    main_kernel<<<NN, 256>>>(scalar, vector, expansion, direction, mask,
                             mR_w, mR_b, uR_w1, uR_b1, uR_w2, uR_b2, U_w, V_w, out);
}